// round 16
// baseline (speedup 1.0000x reference)
#include <cuda_runtime.h>
#include <cuda_bf16.h>
#include <math.h>
#include <stdint.h>

#define BB 16
#define LL 4096
#define CC 512
#define MM (BB*LL)          // 65536
#define KK 1536
#define NCHUNK 24           // K chunks of 64

// ---------------- device scratch ----------------
__device__ float g_xp [(size_t)MM * CC];   // conv output (134 MB)
__device__ float g_wt [CC * KK];           // W[o][tap*512+c], tf32-rounded
__device__ float g_wpT[CC * CC];
__device__ float g_psum[512 * CC];
__device__ float g_psq [512 * CC];
__device__ float g_ps2 [64 * CC];
__device__ float g_pq2 [64 * CC];
__device__ float g_mean[CC];
__device__ float g_rstd[CC];

// ---------------- helpers ----------------
__device__ __forceinline__ uint32_t smem_u32(const void* p) {
    uint32_t a;
    asm("{ .reg .u64 t; cvta.to.shared.u64 t, %1; cvt.u32.u64 %0, t; }" : "=r"(a) : "l"(p));
    return a;
}
__device__ __forceinline__ uint32_t f2tf32(float v) {
    uint32_t r;
    asm("cvt.rna.tf32.f32 %0, %1;" : "=r"(r) : "f"(v));
    return r;
}
__device__ __forceinline__ void lds64(uint32_t a, uint32_t& v0, uint32_t& v1) {
    asm volatile("ld.shared.v2.b32 {%0,%1}, [%2];" : "=r"(v0), "=r"(v1) : "r"(a));
}
__device__ __forceinline__ void mma_tf32(float* d, const uint32_t* a,
                                         uint32_t b0, uint32_t b1) {
    asm volatile(
        "mma.sync.aligned.m16n8k8.row.col.f32.tf32.tf32.f32 "
        "{%0,%1,%2,%3}, {%4,%5,%6,%7}, {%8,%9}, {%0,%1,%2,%3};"
        : "+f"(d[0]), "+f"(d[1]), "+f"(d[2]), "+f"(d[3])
        : "r"(a[0]), "r"(a[1]), "r"(a[2]), "r"(a[3]), "r"(b0), "r"(b1));
}
#define CP_ASYNC(dst, src, sz)                                                        \
    asm volatile("cp.async.cg.shared.global [%0], [%1], 16, %2;"                      \
        :: "r"(dst), "l"(src), "r"(sz))
#define CP_COMMIT() asm volatile("cp.async.commit_group;" ::: "memory")
#define CP_WAIT1()  asm volatile("cp.async.wait_group 1;" ::: "memory")

// 32B-granular XOR swizzle (keeps 16B cp.async alignment); conflict-free for
// the paired lds64 fragment loads below.
__device__ __forceinline__ uint32_t swz(int r, int seg) {
    return (uint32_t)(r * 256 + ((2 * (((seg >> 1) ^ r) & 7) + (seg & 1)) << 4)
                      + ((seg >> 1) & ~7) * 32);
}

// ---------------- prep ----------------
// Natural k storage: g_wt[o][tap*512 + c]; the logical-k remap needs NO
// permutation (fragment pairs are physically adjacent).
__global__ void prep_w(const float* __restrict__ wd) {
    int t = blockIdx.x * blockDim.x + threadIdx.x;   // CC*KK, t = o*KK + klin
    int o = t / KK;
    int klin = t - o * KK;
    int tap = klin >> 9;
    int c = klin & 511;
    g_wt[t] = __uint_as_float(f2tf32(wd[o * KK + c * 3 + tap]));
}
__global__ void prep_wp(const float* __restrict__ wp) {
    int t = blockIdx.x * blockDim.x + threadIdx.x;   // CC*CC
    int o = t & 511, c = t >> 9;
    g_wpT[t] = wp[o * CC + c];
}
__global__ void dummy_k() {}   // keeps GEMM at launch #4 for ncu

// ---------------- tf32 mma GEMM ----------------
// CTA 128M x 256N, BK=64.  8 warps: 2(M) x 4(N), warp tile 64x64.
// Stage 96 KB (A 128x64 f32 + B 256x64 f32, 256B rows, 32B-group swizzle).
// 2 stages = 192 KB + 4 KB stats.  A raw fp32 (HW tf32-truncates), W rna.
// Logical k remap: logical (tig, tig+4) = physical (2tig, 2tig+1) -> all
// fragment loads are 8B lds64, conflict-free under the 32B swizzle.
#define STAGE_BYTES 98304
#define B_OFF       32768
#define SMEM_STATS  (2 * STAGE_BYTES)
#define SMEM_TOTAL_GEMM (SMEM_STATS + 4096)

__device__ __forceinline__ void load_chunk(uint32_t sA, int row0, int col0,
                                           int q, int tid, const float* __restrict__ x) {
    const int k0  = q * 64;
    const int tap = k0 >> 9;
    const int c0  = k0 & 511;
    #pragma unroll
    for (int it = 0; it < 8; ++it) {               // A: 128 rows x 16 segs
        int u = tid + it * 256;
        int r = u >> 4, seg = u & 15;
        int R = row0 + r;
        int l = R & (LL - 1);
        int l2 = l + 2 * tap;
        int valid = (l2 < LL);
        const float* src = x + (size_t)((R - l) + (valid ? l2 : 0)) * CC + c0 + seg * 4;
        CP_ASYNC(sA + swz(r, seg), src, valid ? 16 : 0);
    }
    #pragma unroll
    for (int it = 0; it < 16; ++it) {              // B: 256 n-rows x 16 segs
        int u = tid + it * 256;
        int n = u >> 4, seg = u & 15;
        const float* src = g_wt + (size_t)(col0 + n) * KK + k0 + seg * 4;
        CP_ASYNC(sA + B_OFF + swz(n, seg), src, 16);
    }
}

__global__ __launch_bounds__(256, 1) void conv_gemm_mma(const float* __restrict__ x,
                                                        const float* __restrict__ b_down) {
    extern __shared__ char smem[];
    const uint32_t sbase = smem_u32(smem);
    const int tid  = threadIdx.x;
    const int wid  = tid >> 5;
    const int lane = tid & 31;
    const int col0 = blockIdx.x * 256;
    const int row0 = blockIdx.y * 128;
    const int wm = wid >> 2;          // 0..1 -> 64 M rows
    const int wn = wid & 3;           // 0..3 -> 64 N cols
    const int g   = lane >> 2;        // 0..7 (fragment row group)
    const int tig = lane & 3;         // 0..3 (fragment k slot)

    float acc[4][8][4];
    #pragma unroll
    for (int i = 0; i < 4; ++i)
        #pragma unroll
        for (int j = 0; j < 8; ++j)
            #pragma unroll
            for (int k = 0; k < 4; ++k) acc[i][j][k] = 0.f;

    load_chunk(sbase,               row0, col0, 0, tid, x); CP_COMMIT();
    load_chunk(sbase + STAGE_BYTES, row0, col0, 1, tid, x); CP_COMMIT();

    for (int q = 0; q < NCHUNK; ++q) {
        CP_WAIT1();
        __syncthreads();
        const uint32_t sA = sbase + (q & 1) * STAGE_BYTES;
        const uint32_t sB = sA + B_OFF;

        #pragma unroll
        for (int s = 0; s < 8; ++s) {
            // shared k-offset for all fragment loads this slice:
            // 32B group (s ^ (row&7)) + 8B slot tig
            const uint32_t so = (((uint32_t)(s ^ g)) << 5) + ((uint32_t)tig << 3);
            uint32_t af[4][4];
            #pragma unroll
            for (int mt = 0; mt < 4; ++mt) {
                uint32_t a = sA + (uint32_t)(wm * 64 + mt * 16 + g) * 256 + so;
                lds64(a,        af[mt][0], af[mt][2]);   // rows r:   logical (tig, tig+4)
                lds64(a + 2048, af[mt][1], af[mt][3]);   // rows r+8
            }
            #pragma unroll
            for (int nt = 0; nt < 8; ++nt) {
                uint32_t b0, b1;
                lds64(sB + (uint32_t)(wn * 64 + nt * 8 + g) * 256 + so, b0, b1);
                #pragma unroll
                for (int mt = 0; mt < 4; ++mt)
                    mma_tf32(acc[mt][nt], af[mt], b0, b1);
            }
        }
        __syncthreads();
        if (q + 2 < NCHUNK) {
            load_chunk(sbase + (q & 1) * STAGE_BYTES, row0, col0, q + 2, tid, x);
            CP_COMMIT();
        }
    }

    // ---- epilogue: bias + store + fused per-CTA BN partial stats ----
    float* bufS = reinterpret_cast<float*>(smem + SMEM_STATS);         // [2][256]
    float* bufQ = reinterpret_cast<float*>(smem + SMEM_STATS + 2048);  // [2][256]

    bool mval[4][2];
    #pragma unroll
    for (int mt = 0; mt < 4; ++mt)
        #pragma unroll
        for (int h = 0; h < 2; ++h) {
            int l = (row0 + wm * 64 + mt * 16 + g + h * 8) & (LL - 1);
            mval[mt][h] = (l < LL - 4);     // fixup rows excluded from stats
        }

    #pragma unroll
    for (int nt = 0; nt < 8; ++nt) {
        const int col = col0 + wn * 64 + nt * 8 + tig * 2;
        float bv0 = __ldg(b_down + col), bv1 = __ldg(b_down + col + 1);
        float s0 = 0.f, s1 = 0.f, q0 = 0.f, q1 = 0.f;
        #pragma unroll
        for (int mt = 0; mt < 4; ++mt) {
            const int r0 = row0 + wm * 64 + mt * 16 + g;
            float v00 = acc[mt][nt][0] + bv0, v01 = acc[mt][nt][1] + bv1;
            float v10 = acc[mt][nt][2] + bv0, v11 = acc[mt][nt][3] + bv1;
            *reinterpret_cast<float2*>(g_xp + (size_t)r0 * CC + col)       = make_float2(v00, v01);
            *reinterpret_cast<float2*>(g_xp + (size_t)(r0 + 8) * CC + col) = make_float2(v10, v11);
            if (mval[mt][0]) { s0 += v00; q0 += v00 * v00; s1 += v01; q1 += v01 * v01; }
            if (mval[mt][1]) { s0 += v10; q0 += v10 * v10; s1 += v11; q1 += v11 * v11; }
        }
        #pragma unroll
        for (int off = 4; off < 32; off <<= 1) {
            s0 += __shfl_xor_sync(0xffffffffu, s0, off);
            q0 += __shfl_xor_sync(0xffffffffu, q0, off);
            s1 += __shfl_xor_sync(0xffffffffu, s1, off);
            q1 += __shfl_xor_sync(0xffffffffu, q1, off);
        }
        if (lane < 4) {
            int cl = wn * 64 + nt * 8 + lane * 2;
            bufS[wm * 256 + cl]     = s0;
            bufQ[wm * 256 + cl]     = q0;
            bufS[wm * 256 + cl + 1] = s1;
            bufQ[wm * 256 + cl + 1] = q1;
        }
    }
    __syncthreads();
    if (tid < 256) {
        g_psum[(size_t)blockIdx.y * CC + col0 + tid] = bufS[tid] + bufS[256 + tid];
        g_psq [(size_t)blockIdx.y * CC + col0 + tid] = bufQ[tid] + bufQ[256 + tid];
    }
}

// ---------------- fixup (fp32 exact): rows L-4..L-1 per batch ----------------
__global__ void fixup_kernel(const float* __restrict__ x, const float* __restrict__ b_pad) {
    __shared__ float xr[CC];
    const int b = blockIdx.x >> 2;
    const int p = blockIdx.x & 3;
    const int o = threadIdx.x;
    xr[o] = x[((size_t)b * LL + p) * CC + o];
    __syncthreads();
    float s0 = 0.f, s1 = 0.f, s2 = 0.f, s3 = 0.f;
    #pragma unroll 4
    for (int c = 0; c < CC; c += 4) {
        s0 += xr[c + 0] * g_wpT[(c + 0) * CC + o];
        s1 += xr[c + 1] * g_wpT[(c + 1) * CC + o];
        s2 += xr[c + 2] * g_wpT[(c + 2) * CC + o];
        s3 += xr[c + 3] * g_wpT[(c + 3) * CC + o];
    }
    g_xp[((size_t)b * LL + (LL - 4) + p) * CC + o] =
        b_pad[o] + ((s0 + s1) + (s2 + s3));
}

// ---------------- BN stats: 2-stage reduce of GEMM partials ----------------
__global__ void stats_mid() {
    const int c = threadIdx.x;
    const int k0 = blockIdx.x * 8;                 // 64 blocks x 8 rows
    float s = 0.f, q = 0.f;
    #pragma unroll
    for (int k = 0; k < 8; ++k) {
        s += g_psum[(k0 + k) * CC + c];
        q += g_psq [(k0 + k) * CC + c];
    }
    g_ps2[blockIdx.x * CC + c] = s;
    g_pq2[blockIdx.x * CC + c] = q;
}
__global__ void stats_final() {
    const int c = threadIdx.x;
    float s = 0.f, q = 0.f;
    #pragma unroll 8
    for (int k = 0; k < 64; ++k) {
        s += g_ps2[k * CC + c];
        q += g_pq2[k * CC + c];
    }
    #pragma unroll
    for (int b = 0; b < BB; ++b)
        #pragma unroll
        for (int p = 0; p < 4; ++p) {
            float v = g_xp[((size_t)b * LL + (LL - 4) + p) * CC + c];
            s += v;
            q += v * v;
        }
    const float inv_n = 1.f / (float)MM;
    float mean = s * inv_n;
    float var  = q * inv_n - mean * mean;
    g_mean[c] = mean;
    g_rstd[c] = rsqrtf(var + 1e-5f);
}

// ---------------- fused BN+ELU+residual+maxpool ----------------
__global__ __launch_bounds__(256) void pool_kernel(const float* __restrict__ x,
                                                   const float* __restrict__ gamma,
                                                   const float* __restrict__ beta,
                                                   float* __restrict__ out) {
    int idx = blockIdx.x * blockDim.x + threadIdx.x;
    int c = (idx & 127) << 2;
    int t = (idx >> 7) & 2047;
    int b = idx >> 18;

    float4 mean = *reinterpret_cast<const float4*>(g_mean + c);
    float4 rstd = *reinterpret_cast<const float4*>(g_rstd + c);
    float4 ga   = *reinterpret_cast<const float4*>(gamma + c);
    float4 be   = *reinterpret_cast<const float4*>(beta + c);

    float4 m = make_float4(-INFINITY, -INFINITY, -INFINITY, -INFINITY);
    #pragma unroll
    for (int dl = -1; dl <= 1; ++dl) {
        int l = 2 * t + dl;
        if (l < 0) continue;
        size_t off = ((size_t)b * LL + l) * CC + c;
        float4 xp = *reinterpret_cast<const float4*>(g_xp + off);
        float4 xr = *reinterpret_cast<const float4*>(x + off);
        float v, y;
        v = (xp.x - mean.x) * rstd.x * ga.x + be.x; y = (v > 0.f ? v : expm1f(v)) + xr.x; m.x = fmaxf(m.x, y);
        v = (xp.y - mean.y) * rstd.y * ga.y + be.y; y = (v > 0.f ? v : expm1f(v)) + xr.y; m.y = fmaxf(m.y, y);
        v = (xp.z - mean.z) * rstd.z * ga.z + be.z; y = (v > 0.f ? v : expm1f(v)) + xr.z; m.z = fmaxf(m.z, y);
        v = (xp.w - mean.w) * rstd.w * ga.w + be.w; y = (v > 0.f ? v : expm1f(v)) + xr.w; m.w = fmaxf(m.w, y);
    }
    *reinterpret_cast<float4*>(out + ((size_t)b * 2048 + t) * CC + c) = m;
}

// ---------------------------------------------------------------------------
extern "C" void kernel_launch(void* const* d_in, const int* in_sizes, int n_in,
                              void* d_out, int out_size) {
    const float* x      = (const float*)d_in[0];
    const float* w_down = (const float*)d_in[1];
    const float* b_down = (const float*)d_in[2];
    const float* w_pad  = (const float*)d_in[3];
    const float* b_pad  = (const float*)d_in[4];
    const float* gamma  = (const float*)d_in[5];
    const float* beta   = (const float*)d_in[6];
    float* out = (float*)d_out;
    (void)in_sizes; (void)n_in; (void)out_size;

    cudaFuncSetAttribute(conv_gemm_mma, cudaFuncAttributeMaxDynamicSharedMemorySize,
                         SMEM_TOTAL_GEMM);

    prep_w <<<CC * KK / 256, 256>>>(w_down);     // #1
    prep_wp<<<CC * CC / 256, 256>>>(w_pad);      // #2
    dummy_k<<<1, 32>>>();                        // #3

    dim3 grid(2, 512);                           // (N blocks of 256, M blocks of 128)
    conv_gemm_mma<<<grid, 256, SMEM_TOTAL_GEMM>>>(x, b_down);   // #4 <- profiled

    fixup_kernel<<<BB * 4, CC>>>(x, b_pad);
    stats_mid<<<64, CC>>>();
    stats_final<<<1, CC>>>();
    pool_kernel<<<(BB * 2048 * (CC / 4)) / 256, 256>>>(x, gamma, beta, out);
}

// round 17
// speedup vs baseline: 1.0603x; 1.0603x over previous
#include <cuda_runtime.h>
#include <cuda_bf16.h>
#include <math.h>
#include <stdint.h>

#define BB 16
#define LL 4096
#define CC 512
#define MM (BB*LL)          // 65536
#define KK 1536
#define NCHUNK 24           // K chunks of 64

// ---------------- device scratch ----------------
__device__ float g_xp [(size_t)MM * CC];   // conv output (134 MB)
__device__ float g_wt [CC * KK];           // W[o][tap*512+c], tf32-rounded
__device__ float g_wpT[CC * CC];
__device__ float g_psum[512 * CC];
__device__ float g_psq [512 * CC];
__device__ float g_ps2 [64 * CC];
__device__ float g_pq2 [64 * CC];
__device__ float g_mean[CC];
__device__ float g_rstd[CC];

// ---------------- helpers ----------------
__device__ __forceinline__ uint32_t smem_u32(const void* p) {
    uint32_t a;
    asm("{ .reg .u64 t; cvta.to.shared.u64 t, %1; cvt.u32.u64 %0, t; }" : "=r"(a) : "l"(p));
    return a;
}
__device__ __forceinline__ uint32_t f2tf32(float v) {
    uint32_t r;
    asm("cvt.rna.tf32.f32 %0, %1;" : "=r"(r) : "f"(v));
    return r;
}
#define LDMX4(r, a)                                                                   \
    asm volatile("ldmatrix.sync.aligned.m8n8.x4.shared.b16 {%0,%1,%2,%3}, [%4];"      \
        : "=r"((r)[0]), "=r"((r)[1]), "=r"((r)[2]), "=r"((r)[3]) : "r"(a))
__device__ __forceinline__ void mma_tf32(float* d, const uint32_t* a,
                                         uint32_t b0, uint32_t b1) {
    asm volatile(
        "mma.sync.aligned.m16n8k8.row.col.f32.tf32.tf32.f32 "
        "{%0,%1,%2,%3}, {%4,%5,%6,%7}, {%8,%9}, {%0,%1,%2,%3};"
        : "+f"(d[0]), "+f"(d[1]), "+f"(d[2]), "+f"(d[3])
        : "r"(a[0]), "r"(a[1]), "r"(a[2]), "r"(a[3]), "r"(b0), "r"(b1));
}
#define CP_ASYNC(dst, src, sz)                                                        \
    asm volatile("cp.async.cg.shared.global [%0], [%1], 16, %2;"                      \
        :: "r"(dst), "l"(src), "r"(sz))
#define CP_COMMIT() asm volatile("cp.async.commit_group;" ::: "memory")
#define CP_WAIT1()  asm volatile("cp.async.wait_group 1;" ::: "memory")

// ---------------- prep ----------------
__global__ void prep_w(const float* __restrict__ wd) {
    int t = blockIdx.x * blockDim.x + threadIdx.x;   // CC*KK, t = o*KK + klin
    int o = t / KK;
    int klin = t - o * KK;
    int tap = klin >> 9;
    int c = klin & 511;
    g_wt[t] = __uint_as_float(f2tf32(wd[o * KK + c * 3 + tap]));
}
__global__ void prep_wp(const float* __restrict__ wp) {
    int t = blockIdx.x * blockDim.x + threadIdx.x;   // CC*CC
    int o = t & 511, c = t >> 9;
    g_wpT[t] = wp[o * CC + c];
}
__global__ void dummy_k() {}   // keeps GEMM at launch #4 for ncu

// ---------------- tf32 mma GEMM (ldmatrix fragments) ----------------
// CTA 128M x 256N, BK=64.  8 warps: 2(M) x 4(N), warp tile 64x64.
// Stage 96 KB: A 128x64 f32 + B 256x64 f32; rows 256B = 16 segs of 16B,
// swizzle phys_seg = seg ^ (r & 7)  (conflict-free for ldmatrix row groups).
// 2 stages = 192 KB + 4 KB stats.  A raw fp32 (HW tf32-truncates), W rna.
#define STAGE_BYTES 98304
#define B_OFF       32768
#define SMEM_STATS  (2 * STAGE_BYTES)
#define SMEM_TOTAL_GEMM (SMEM_STATS + 4096)

__device__ __forceinline__ void load_chunk(uint32_t sA, int row0, int col0,
                                           int q, int tid, const float* __restrict__ x) {
    const int k0  = q * 64;
    const int tap = k0 >> 9;
    const int c0  = k0 & 511;
    #pragma unroll
    for (int it = 0; it < 8; ++it) {               // A: 128 rows x 16 segs
        int u = tid + it * 256;
        int r = u >> 4, seg = u & 15;
        int R = row0 + r;
        int l = R & (LL - 1);
        int l2 = l + 2 * tap;
        int valid = (l2 < LL);
        const float* src = x + (size_t)((R - l) + (valid ? l2 : 0)) * CC + c0 + seg * 4;
        uint32_t dst = sA + r * 256 + ((seg ^ (r & 7)) << 4);
        CP_ASYNC(dst, src, valid ? 16 : 0);
    }
    #pragma unroll
    for (int it = 0; it < 16; ++it) {              // B: 256 n-rows x 16 segs
        int u = tid + it * 256;
        int n = u >> 4, seg = u & 15;
        const float* src = g_wt + (size_t)(col0 + n) * KK + k0 + seg * 4;
        uint32_t dst = sA + B_OFF + n * 256 + ((seg ^ (n & 7)) << 4);
        CP_ASYNC(dst, src, 16);
    }
}

__global__ __launch_bounds__(256, 1) void conv_gemm_mma(const float* __restrict__ x,
                                                        const float* __restrict__ b_down) {
    extern __shared__ char smem[];
    const uint32_t sbase = smem_u32(smem);
    const int tid  = threadIdx.x;
    const int wid  = tid >> 5;
    const int lane = tid & 31;
    const int col0 = blockIdx.x * 256;
    const int row0 = blockIdx.y * 128;
    const int wm = wid >> 2;          // 0..1 -> 64 M rows
    const int wn = wid & 3;           // 0..3 -> 64 N cols
    const int g   = lane >> 2;        // 0..7
    const int tig = lane & 3;         // 0..3

    // ldmatrix per-lane row addressing:
    // tile t = lane>>3; rows: arow = (lane&7) + ((lane>>3)&1)*8; k half: seghi = lane>>4
    const int arow   = (lane & 7) + ((lane >> 3) & 1) * 8;
    const int seghi  = lane >> 4;
    const uint32_t r7 = (uint32_t)(lane & 7);      // (base+arow) & 7 == lane & 7

    uint32_t aoff[4], boff[4];
    #pragma unroll
    for (int mt = 0; mt < 4; ++mt)
        aoff[mt] = (uint32_t)(wm * 64 + mt * 16 + arow) * 256;
    #pragma unroll
    for (int p = 0; p < 4; ++p)
        boff[p] = (uint32_t)(B_OFF + (wn * 64 + p * 16 + arow) * 256);

    float acc[4][8][4];
    #pragma unroll
    for (int i = 0; i < 4; ++i)
        #pragma unroll
        for (int j = 0; j < 8; ++j)
            #pragma unroll
            for (int k = 0; k < 4; ++k) acc[i][j][k] = 0.f;

    load_chunk(sbase,               row0, col0, 0, tid, x); CP_COMMIT();
    load_chunk(sbase + STAGE_BYTES, row0, col0, 1, tid, x); CP_COMMIT();

    for (int q = 0; q < NCHUNK; ++q) {
        CP_WAIT1();
        __syncthreads();
        const uint32_t sA = sbase + (q & 1) * STAGE_BYTES;

        #pragma unroll
        for (int s = 0; s < 8; ++s) {
            const uint32_t soff = (((uint32_t)(2 * s + seghi)) ^ r7) << 4;
            uint32_t af[4][4], bp[4][4];
            #pragma unroll
            for (int mt = 0; mt < 4; ++mt)
                LDMX4(af[mt], sA + aoff[mt] + soff);
            #pragma unroll
            for (int p = 0; p < 4; ++p)
                LDMX4(bp[p], sA + boff[p] + soff);
            #pragma unroll
            for (int nt = 0; nt < 8; ++nt) {
                const uint32_t b0 = bp[nt >> 1][nt & 1];
                const uint32_t b1 = bp[nt >> 1][2 + (nt & 1)];
                #pragma unroll
                for (int mt = 0; mt < 4; ++mt)
                    mma_tf32(acc[mt][nt], af[mt], b0, b1);
            }
        }
        __syncthreads();
        if (q + 2 < NCHUNK) {
            load_chunk(sbase + (q & 1) * STAGE_BYTES, row0, col0, q + 2, tid, x);
            CP_COMMIT();
        }
    }

    // ---- epilogue: bias + store + fused per-CTA BN partial stats ----
    float* bufS = reinterpret_cast<float*>(smem + SMEM_STATS);         // [2][256]
    float* bufQ = reinterpret_cast<float*>(smem + SMEM_STATS + 2048);  // [2][256]

    bool mval[4][2];
    #pragma unroll
    for (int mt = 0; mt < 4; ++mt)
        #pragma unroll
        for (int h = 0; h < 2; ++h) {
            int l = (row0 + wm * 64 + mt * 16 + g + h * 8) & (LL - 1);
            mval[mt][h] = (l < LL - 4);     // fixup rows excluded from stats
        }

    #pragma unroll
    for (int nt = 0; nt < 8; ++nt) {
        const int col = col0 + wn * 64 + nt * 8 + tig * 2;
        float bv0 = __ldg(b_down + col), bv1 = __ldg(b_down + col + 1);
        float s0 = 0.f, s1 = 0.f, q0 = 0.f, q1 = 0.f;
        #pragma unroll
        for (int mt = 0; mt < 4; ++mt) {
            const int r0 = row0 + wm * 64 + mt * 16 + g;
            float v00 = acc[mt][nt][0] + bv0, v01 = acc[mt][nt][1] + bv1;
            float v10 = acc[mt][nt][2] + bv0, v11 = acc[mt][nt][3] + bv1;
            *reinterpret_cast<float2*>(g_xp + (size_t)r0 * CC + col)       = make_float2(v00, v01);
            *reinterpret_cast<float2*>(g_xp + (size_t)(r0 + 8) * CC + col) = make_float2(v10, v11);
            if (mval[mt][0]) { s0 += v00; q0 += v00 * v00; s1 += v01; q1 += v01 * v01; }
            if (mval[mt][1]) { s0 += v10; q0 += v10 * v10; s1 += v11; q1 += v11 * v11; }
        }
        #pragma unroll
        for (int off = 4; off < 32; off <<= 1) {
            s0 += __shfl_xor_sync(0xffffffffu, s0, off);
            q0 += __shfl_xor_sync(0xffffffffu, q0, off);
            s1 += __shfl_xor_sync(0xffffffffu, s1, off);
            q1 += __shfl_xor_sync(0xffffffffu, q1, off);
        }
        if (lane < 4) {
            int cl = wn * 64 + nt * 8 + lane * 2;
            bufS[wm * 256 + cl]     = s0;
            bufQ[wm * 256 + cl]     = q0;
            bufS[wm * 256 + cl + 1] = s1;
            bufQ[wm * 256 + cl + 1] = q1;
        }
    }
    __syncthreads();
    if (tid < 256) {
        g_psum[(size_t)blockIdx.y * CC + col0 + tid] = bufS[tid] + bufS[256 + tid];
        g_psq [(size_t)blockIdx.y * CC + col0 + tid] = bufQ[tid] + bufQ[256 + tid];
    }
}

// ---------------- fixup (fp32 exact): rows L-4..L-1 per batch ----------------
__global__ void fixup_kernel(const float* __restrict__ x, const float* __restrict__ b_pad) {
    __shared__ float xr[CC];
    const int b = blockIdx.x >> 2;
    const int p = blockIdx.x & 3;
    const int o = threadIdx.x;
    xr[o] = x[((size_t)b * LL + p) * CC + o];
    __syncthreads();
    float s0 = 0.f, s1 = 0.f, s2 = 0.f, s3 = 0.f;
    #pragma unroll 4
    for (int c = 0; c < CC; c += 4) {
        s0 += xr[c + 0] * g_wpT[(c + 0) * CC + o];
        s1 += xr[c + 1] * g_wpT[(c + 1) * CC + o];
        s2 += xr[c + 2] * g_wpT[(c + 2) * CC + o];
        s3 += xr[c + 3] * g_wpT[(c + 3) * CC + o];
    }
    g_xp[((size_t)b * LL + (LL - 4) + p) * CC + o] =
        b_pad[o] + ((s0 + s1) + (s2 + s3));
}

// ---------------- BN stats: 2-stage reduce of GEMM partials ----------------
__global__ void stats_mid() {
    const int c = threadIdx.x;
    const int k0 = blockIdx.x * 8;                 // 64 blocks x 8 rows
    float s = 0.f, q = 0.f;
    #pragma unroll
    for (int k = 0; k < 8; ++k) {
        s += g_psum[(k0 + k) * CC + c];
        q += g_psq [(k0 + k) * CC + c];
    }
    g_ps2[blockIdx.x * CC + c] = s;
    g_pq2[blockIdx.x * CC + c] = q;
}
__global__ void stats_final() {
    const int c = threadIdx.x;
    float s = 0.f, q = 0.f;
    #pragma unroll 8
    for (int k = 0; k < 64; ++k) {
        s += g_ps2[k * CC + c];
        q += g_pq2[k * CC + c];
    }
    #pragma unroll
    for (int b = 0; b < BB; ++b)
        #pragma unroll
        for (int p = 0; p < 4; ++p) {
            float v = g_xp[((size_t)b * LL + (LL - 4) + p) * CC + c];
            s += v;
            q += v * v;
        }
    const float inv_n = 1.f / (float)MM;
    float mean = s * inv_n;
    float var  = q * inv_n - mean * mean;
    g_mean[c] = mean;
    g_rstd[c] = rsqrtf(var + 1e-5f);
}

// ---------------- fused BN+ELU+residual+maxpool ----------------
__global__ __launch_bounds__(256) void pool_kernel(const float* __restrict__ x,
                                                   const float* __restrict__ gamma,
                                                   const float* __restrict__ beta,
                                                   float* __restrict__ out) {
    int idx = blockIdx.x * blockDim.x + threadIdx.x;
    int c = (idx & 127) << 2;
    int t = (idx >> 7) & 2047;
    int b = idx >> 18;

    float4 mean = *reinterpret_cast<const float4*>(g_mean + c);
    float4 rstd = *reinterpret_cast<const float4*>(g_rstd + c);
    float4 ga   = *reinterpret_cast<const float4*>(gamma + c);
    float4 be   = *reinterpret_cast<const float4*>(beta + c);

    float4 m = make_float4(-INFINITY, -INFINITY, -INFINITY, -INFINITY);
    #pragma unroll
    for (int dl = -1; dl <= 1; ++dl) {
        int l = 2 * t + dl;
        if (l < 0) continue;
        size_t off = ((size_t)b * LL + l) * CC + c;
        float4 xp = *reinterpret_cast<const float4*>(g_xp + off);
        float4 xr = *reinterpret_cast<const float4*>(x + off);
        float v, y;
        v = (xp.x - mean.x) * rstd.x * ga.x + be.x; y = (v > 0.f ? v : expm1f(v)) + xr.x; m.x = fmaxf(m.x, y);
        v = (xp.y - mean.y) * rstd.y * ga.y + be.y; y = (v > 0.f ? v : expm1f(v)) + xr.y; m.y = fmaxf(m.y, y);
        v = (xp.z - mean.z) * rstd.z * ga.z + be.z; y = (v > 0.f ? v : expm1f(v)) + xr.z; m.z = fmaxf(m.z, y);
        v = (xp.w - mean.w) * rstd.w * ga.w + be.w; y = (v > 0.f ? v : expm1f(v)) + xr.w; m.w = fmaxf(m.w, y);
    }
    *reinterpret_cast<float4*>(out + ((size_t)b * 2048 + t) * CC + c) = m;
}

// ---------------------------------------------------------------------------
extern "C" void kernel_launch(void* const* d_in, const int* in_sizes, int n_in,
                              void* d_out, int out_size) {
    const float* x      = (const float*)d_in[0];
    const float* w_down = (const float*)d_in[1];
    const float* b_down = (const float*)d_in[2];
    const float* w_pad  = (const float*)d_in[3];
    const float* b_pad  = (const float*)d_in[4];
    const float* gamma  = (const float*)d_in[5];
    const float* beta   = (const float*)d_in[6];
    float* out = (float*)d_out;
    (void)in_sizes; (void)n_in; (void)out_size;

    cudaFuncSetAttribute(conv_gemm_mma, cudaFuncAttributeMaxDynamicSharedMemorySize,
                         SMEM_TOTAL_GEMM);

    prep_w <<<CC * KK / 256, 256>>>(w_down);     // #1
    prep_wp<<<CC * CC / 256, 256>>>(w_pad);      // #2
    dummy_k<<<1, 32>>>();                        // #3

    dim3 grid(2, 512);                           // (N blocks of 256, M blocks of 128)
    conv_gemm_mma<<<grid, 256, SMEM_TOTAL_GEMM>>>(x, b_down);   // #4 <- profiled

    fixup_kernel<<<BB * 4, CC>>>(x, b_pad);
    stats_mid<<<64, CC>>>();
    stats_final<<<1, CC>>>();
    pool_kernel<<<(BB * 2048 * (CC / 4)) / 256, 256>>>(x, gamma, beta, out);
}